// round 9
// baseline (speedup 1.0000x reference)
#include <cuda_runtime.h>
#include <math.h>
#include <stdint.h>

// Problem constants
#define N_TOK   2048
#define DIM     512
#define POOLSZ  65536
#define HIDDEN  256
#define CHID    128
#define KSEL    256
#define CAND2   2048        // candidate buffer depth per token
#define FLOORZ  2.4f        // floor = FLOORZ * sigma_token  (E[count]=537, sd=23)

// GEMM tiling
#define BM 128
#define BN 256
#define BK 32
#define SA (BM * 36)        // As stage stride (floats), pad 36
#define SB (BK * 260)       // Bs stage stride (floats), pad 260
#define GEMM_SMEM_FLOATS (2 * SA + 2 * SB + BN + BM)
#define GEMM_SMEM_BYTES  (GEMM_SMEM_FLOATS * 4)

// Device scratch
__device__ float              g_h[N_TOK * HIDDEN];
__device__ float              g_floor[N_TOK];
__device__ unsigned           g_ccnt[N_TOK];
__device__ unsigned long long g_cand[(size_t)N_TOK * CAND2];
__device__ int                g_budget[N_TOK];
__device__ int                g_topidx[N_TOK * KSEL];
__device__ float              g_topw[N_TOK * KSEL];

// key helpers: monotonic float->uint mapping
__device__ __forceinline__ unsigned f2key(float s) {
    unsigned u = __float_as_uint(s);
    return (u & 0x80000000u) ? ~u : (u | 0x80000000u);
}
__device__ __forceinline__ float key2f(unsigned k) {
    return (k & 0x80000000u) ? __uint_as_float(k ^ 0x80000000u)
                             : __uint_as_float(~k);
}
// pack: sort desc by key; ties -> smaller index first (matches jax top_k)
__device__ __forceinline__ unsigned long long packc(unsigned key, unsigned idx) {
    return ((unsigned long long)key << 32) | (unsigned long long)(0xFFFFFFFFu - idx);
}

__device__ __forceinline__ void cp_async16(uint32_t saddr, const void* gaddr) {
    asm volatile("cp.async.cg.shared.global [%0], [%1], 16;\n"
                 :: "r"(saddr), "l"(gaddr));
}
__device__ __forceinline__ void cp_commit() {
    asm volatile("cp.async.commit_group;\n");
}
template <int N> __device__ __forceinline__ void cp_wait() {
    asm volatile("cp.async.wait_group %0;\n" :: "n"(N));
}

__device__ __forceinline__ void mma_tf32(float* d, const uint32_t* a, const uint32_t* b) {
    asm volatile(
        "mma.sync.aligned.m16n8k8.row.col.f32.tf32.tf32.f32 "
        "{%0,%1,%2,%3}, {%4,%5,%6,%7}, {%8,%9}, {%0,%1,%2,%3};"
        : "+f"(d[0]), "+f"(d[1]), "+f"(d[2]), "+f"(d[3])
        : "r"(a[0]), "r"(a[1]), "r"(a[2]), "r"(a[3]), "r"(b[0]), "r"(b[1]));
}

// ---------------------------------------------------------------------------
// zero candidate counters (graph-replay safe)
// ---------------------------------------------------------------------------
__global__ void zero_kernel() {
    int i = blockIdx.x * blockDim.x + threadIdx.x;
    if (i < N_TOK) g_ccnt[i] = 0;
}

// ---------------------------------------------------------------------------
// Kernel 1: complexity net -> budget[token]
// ---------------------------------------------------------------------------
__global__ void budget_kernel(const float* __restrict__ x,
                              const float* __restrict__ Wc1,
                              const float* __restrict__ bc1,
                              const float* __restrict__ Wc2,
                              const float* __restrict__ bc2) {
    __shared__ float xs[16][DIM];
    __shared__ float red[16][CHID];
    int tid = threadIdx.x;            // 0..127
    int t0  = blockIdx.x * 16;

    const float4* xsrc = (const float4*)(x + (size_t)t0 * DIM);
    float4* xdst = (float4*)&xs[0][0];
    for (int i = tid; i < 16 * DIM / 4; i += 128) xdst[i] = xsrc[i];
    __syncthreads();

    float acc[16];
#pragma unroll
    for (int m = 0; m < 16; m++) acc[m] = 0.f;

    for (int i = 0; i < DIM; i += 4) {
        float w0 = Wc1[(i + 0) * CHID + tid];
        float w1 = Wc1[(i + 1) * CHID + tid];
        float w2 = Wc1[(i + 2) * CHID + tid];
        float w3 = Wc1[(i + 3) * CHID + tid];
#pragma unroll
        for (int m = 0; m < 16; m++) {
            float4 xv = *(const float4*)&xs[m][i];
            acc[m] += xv.x * w0 + xv.y * w1 + xv.z * w2 + xv.w * w3;
        }
    }

    float b1  = bc1[tid];
    float wc2 = Wc2[tid];
#pragma unroll
    for (int m = 0; m < 16; m++) red[m][tid] = fmaxf(acc[m] + b1, 0.f) * wc2;
    __syncthreads();

    if (tid < 16) {
        float s = bc2[0];
        for (int t = 0; t < CHID; t++) s += red[tid][t];
        float sig   = 1.f / (1.f + expf(-s));
        float scale = sig * sig;
        float raw   = 100.f + 156.f * scale;
        raw = fminf(fmaxf(raw, 100.f), 256.f);
        g_budget[t0 + tid] = (int)rintf(raw);
    }
}

// ---------------------------------------------------------------------------
// Kernel 2: scorer hidden h = relu(x @ Ws1 + bs1)
// ---------------------------------------------------------------------------
__global__ void hidden_kernel(const float* __restrict__ x,
                              const float* __restrict__ Ws1,
                              const float* __restrict__ bs1) {
    __shared__ float xs[16][DIM];
    int tid = threadIdx.x;            // 0..255
    int t0  = blockIdx.x * 16;

    const float4* xsrc = (const float4*)(x + (size_t)t0 * DIM);
    float4* xdst = (float4*)&xs[0][0];
    for (int i = tid; i < 16 * DIM / 4; i += 256) xdst[i] = xsrc[i];
    __syncthreads();

    float acc[16];
#pragma unroll
    for (int m = 0; m < 16; m++) acc[m] = 0.f;

    for (int i = 0; i < DIM; i += 4) {
        float w0 = Ws1[(i + 0) * HIDDEN + tid];
        float w1 = Ws1[(i + 1) * HIDDEN + tid];
        float w2 = Ws1[(i + 2) * HIDDEN + tid];
        float w3 = Ws1[(i + 3) * HIDDEN + tid];
#pragma unroll
        for (int m = 0; m < 16; m++) {
            float4 xv = *(const float4*)&xs[m][i];
            acc[m] += xv.x * w0 + xv.y * w1 + xv.z * w2 + xv.w * w3;
        }
    }

    float b = bs1[tid];
#pragma unroll
    for (int m = 0; m < 16; m++)
        g_h[(size_t)(t0 + m) * HIDDEN + tid] = fmaxf(acc[m] + b, 0.f);
}

// ---------------------------------------------------------------------------
// Kernel 2b: per-token candidate floor = FLOORZ * ||h|| / 16
// (score | h  is exactly N(bias, ||h||^2/256) for i.i.d. normal Ws2 columns)
// ---------------------------------------------------------------------------
__global__ void floor_kernel() {
    int tok  = blockIdx.x * 8 + (threadIdx.x >> 5);
    int lane = threadIdx.x & 31;
    const float* h = g_h + (size_t)tok * HIDDEN;
    float s = 0.f;
    for (int i = lane; i < HIDDEN; i += 32) { float v = h[i]; s += v * v; }
#pragma unroll
    for (int off = 16; off > 0; off >>= 1)
        s += __shfl_xor_sync(0xffffffffu, s, off);
    if (lane == 0) g_floor[tok] = FLOORZ * sqrtf(s) * (1.0f / 16.0f);
}

// ---------------------------------------------------------------------------
// Kernel 3: tf32 tensor-core GEMM with fused candidate filter.
// CTA 128x256, BK=32, 8 warps (2m x 4n), warp tile 64x64,
// cp.async double-buffered stages, fp32 bits fed to tf32 MMA (HW truncation).
// Epilogue: score >= floor[token] -> push packed candidate; no score store.
// ---------------------------------------------------------------------------
__global__ __launch_bounds__(256, 1) void gemm_kernel(const float* __restrict__ Ws2,
                                                      const float* __restrict__ bs2) {
    extern __shared__ float smem[];
    float* bias_s  = smem + 2 * SA + 2 * SB;
    float* floor_s = bias_s + BN;

    int tid  = threadIdx.x;
    int warp = tid >> 5, lane = tid & 31;
    int wm = warp >> 2, wn = warp & 3;     // 2 x 4 warps
    int g  = lane >> 2, tg = lane & 3;
    int m0 = blockIdx.x * BM;
    int n0 = blockIdx.y * BN;

    for (int i = tid; i < BN; i += 256) bias_s[i]  = bs2[n0 + i];
    for (int i = tid; i < BM; i += 256) floor_s[i] = g_floor[m0 + i];

    uint32_t sbase = (uint32_t)__cvta_generic_to_shared(smem);
    const float* gA = g_h + (size_t)m0 * HIDDEN;
    const float* gB = Ws2 + n0;

    int arow = tid >> 3;                   // A: rows arow + {0,32,64,96}
    int ak4  = (tid & 7) << 2;
    int bk   = tid >> 5;                   // B: k rows bk + {0,8,...,56}? (BK=32 -> +{0,8,16,24})
    int bn4  = (tid & 31) << 2;

    // prologue: stage 0
#pragma unroll
    for (int i = 0; i < 4; i++) {
        int row = arow + i * 32;
        cp_async16(sbase + (uint32_t)((row * 36 + ak4) * 4),
                   gA + (size_t)row * HIDDEN + ak4);
    }
#pragma unroll
    for (int i = 0; i < 8; i++) {
        int k = bk + i * 8;
        if (k < BK)
            cp_async16(sbase + (uint32_t)((2 * SA + k * 260 + bn4) * 4),
                       gB + (size_t)k * POOLSZ + bn4);
    }
    cp_commit();

    float acc[4][8][4];
#pragma unroll
    for (int mt = 0; mt < 4; mt++)
#pragma unroll
        for (int nt = 0; nt < 8; nt++)
#pragma unroll
            for (int c = 0; c < 4; c++) acc[mt][nt][c] = 0.f;

    for (int it = 0; it < HIDDEN / BK; it++) {
        int buf = it & 1;
        if (it < HIDDEN / BK - 1) {
            int kb   = (it + 1) * BK;
            int nbuf = buf ^ 1;
#pragma unroll
            for (int i = 0; i < 4; i++) {
                int row = arow + i * 32;
                cp_async16(sbase + (uint32_t)((nbuf * SA + row * 36 + ak4) * 4),
                           gA + (size_t)row * HIDDEN + kb + ak4);
            }
#pragma unroll
            for (int i = 0; i < 8; i++) {
                int k = bk + i * 8;
                if (k < BK)
                    cp_async16(sbase + (uint32_t)((2 * SA + nbuf * SB + k * 260 + bn4) * 4),
                               gB + (size_t)(kb + k) * POOLSZ + bn4);
            }
            cp_commit();
            cp_wait<1>();
        } else {
            cp_wait<0>();
        }
        __syncthreads();

        const float* Ab = smem + buf * SA;
        const float* Bb = smem + 2 * SA + buf * SB;

#pragma unroll
        for (int kk = 0; kk < BK; kk += 8) {
            uint32_t af[4][4];
#pragma unroll
            for (int mt = 0; mt < 4; mt++) {
                int mm = wm * 64 + mt * 16;
                af[mt][0] = __float_as_uint(Ab[(mm + g) * 36 + kk + tg]);
                af[mt][1] = __float_as_uint(Ab[(mm + g + 8) * 36 + kk + tg]);
                af[mt][2] = __float_as_uint(Ab[(mm + g) * 36 + kk + tg + 4]);
                af[mt][3] = __float_as_uint(Ab[(mm + g + 8) * 36 + kk + tg + 4]);
            }
            uint32_t bf[8][2];
#pragma unroll
            for (int nt = 0; nt < 8; nt++) {
                int nn = wn * 64 + nt * 8;
                bf[nt][0] = __float_as_uint(Bb[(kk + tg) * 260 + nn + g]);
                bf[nt][1] = __float_as_uint(Bb[(kk + tg + 4) * 260 + nn + g]);
            }
#pragma unroll
            for (int mt = 0; mt < 4; mt++)
#pragma unroll
                for (int nt = 0; nt < 8; nt++)
                    mma_tf32(acc[mt][nt], af[mt], bf[nt]);
        }
        __syncthreads();
    }

    // epilogue: bias + candidate filter (no score store)
#pragma unroll
    for (int mt = 0; mt < 4; mt++) {
#pragma unroll
        for (int c = 0; c < 4; c++) {
            int m_loc = wm * 64 + mt * 16 + g + ((c & 2) ? 8 : 0);
            float flo = floor_s[m_loc];
            int m = m0 + m_loc;
#pragma unroll
            for (int nt = 0; nt < 8; nt++) {
                int n_loc = wn * 64 + nt * 8 + 2 * tg + (c & 1);
                float s = acc[mt][nt][c] + bias_s[n_loc];
                if (s >= flo) {
                    unsigned pos = atomicAdd(&g_ccnt[m], 1u);
                    if (pos < CAND2)
                        g_cand[(size_t)m * CAND2 + pos] =
                            packc(f2key(s), (unsigned)(n0 + n_loc));
                }
            }
        }
    }
}

// ---------------------------------------------------------------------------
// Kernel 3b: fallback for tokens whose candidate count is out of range.
// Recomputes the full score row (fp32) + exact 13-bit histogram select,
// rewrites the candidate buffer. Early-exits in the normal case.
// ---------------------------------------------------------------------------
#define HB 8192
__global__ void fallback_kernel(const float* __restrict__ Ws2,
                                const float* __restrict__ bs2) {
    int tok = blockIdx.x;
    unsigned cnt0 = g_ccnt[tok];
    if (cnt0 >= KSEL && cnt0 <= CAND2) return;

    __shared__ float    hs[HIDDEN];
    __shared__ unsigned hist[HB];
    __shared__ unsigned bsum[256];
    __shared__ unsigned s_thresh, s_cnt;
    int tid = threadIdx.x;            // 0..255

    for (int i = tid; i < HIDDEN; i += 256) hs[i] = g_h[(size_t)tok * HIDDEN + i];
    for (int i = tid; i < HB; i += 256) hist[i] = 0;
    if (tid == 0) s_cnt = 0;
    __syncthreads();

    // pass 1: histogram of recomputed scores
    for (int j0 = 0; j0 < POOLSZ; j0 += 256) {
        int j = j0 + tid;
        float s = bs2[j];
        for (int k = 0; k < HIDDEN; k += 4) {
            float4 hv = *(const float4*)&hs[k];
            s += hv.x * Ws2[(size_t)(k + 0) * POOLSZ + j];
            s += hv.y * Ws2[(size_t)(k + 1) * POOLSZ + j];
            s += hv.z * Ws2[(size_t)(k + 2) * POOLSZ + j];
            s += hv.w * Ws2[(size_t)(k + 3) * POOLSZ + j];
        }
        atomicAdd(&hist[f2key(s) >> 19], 1u);
    }
    __syncthreads();

    unsigned local = 0;
    int base = tid * 32;
#pragma unroll
    for (int b = 0; b < 32; b++) local += hist[base + b];
    bsum[tid] = local;
    __syncthreads();
    if (tid == 0) {
        unsigned cum = 0;
        int blk = 255;
        for (; blk > 0; blk--) {
            if (cum + bsum[blk] >= KSEL) break;
            cum += bsum[blk];
        }
        int b = blk * 32 + 31;
        for (;; b--) {
            unsigned c = hist[b];
            if (cum + c >= KSEL || b == 0) break;
            cum += c;
        }
        s_thresh = (unsigned)b << 19;
    }
    __syncthreads();
    unsigned th = s_thresh;

    // pass 2: recompute + collect
    for (int j0 = 0; j0 < POOLSZ; j0 += 256) {
        int j = j0 + tid;
        float s = bs2[j];
        for (int k = 0; k < HIDDEN; k += 4) {
            float4 hv = *(const float4*)&hs[k];
            s += hv.x * Ws2[(size_t)(k + 0) * POOLSZ + j];
            s += hv.y * Ws2[(size_t)(k + 1) * POOLSZ + j];
            s += hv.z * Ws2[(size_t)(k + 2) * POOLSZ + j];
            s += hv.w * Ws2[(size_t)(k + 3) * POOLSZ + j];
        }
        unsigned key = f2key(s);
        if (key >= th) {
            unsigned pos = atomicAdd(&s_cnt, 1u);
            if (pos < CAND2)
                g_cand[(size_t)tok * CAND2 + pos] = packc(key, (unsigned)j);
        }
    }
    __syncthreads();
    if (tid == 0) {
        unsigned c = s_cnt;
        g_ccnt[tok] = (c > CAND2) ? CAND2 : c;
    }
}

// ---------------------------------------------------------------------------
// Kernel 4: per-token select: bitonic sort of <=2048 packed candidates,
// softmax over top-256, budget mask.
// ---------------------------------------------------------------------------
#define TPS 512
__global__ void select_kernel() {
    __shared__ unsigned long long c[CAND2];   // 16 KB
    __shared__ float red[256];
    int tid = threadIdx.x;                    // 0..511
    int tok = blockIdx.x;

    unsigned cnt = g_ccnt[tok];
    if (cnt > CAND2) cnt = CAND2;
    for (int i = tid; i < CAND2; i += TPS)
        c[i] = (i < (int)cnt) ? g_cand[(size_t)tok * CAND2 + i] : 0ULL;
    __syncthreads();

    // bitonic sort ascending (largest at CAND2-1)
    for (unsigned k = 2; k <= CAND2; k <<= 1) {
        for (unsigned j = k >> 1; j > 0; j >>= 1) {
            for (unsigned i = tid; i < CAND2; i += TPS) {
                unsigned ixj = i ^ j;
                if (ixj > i) {
                    bool up = ((i & k) == 0);
                    unsigned long long a = c[i], b = c[ixj];
                    if (up ? (a > b) : (a < b)) { c[i] = b; c[ixj] = a; }
                }
            }
            __syncthreads();
        }
    }

    int bud = g_budget[tok];
    float smax = key2f((unsigned)(c[CAND2 - 1] >> 32));
    float ex = 0.f;
    unsigned long long v = 0ULL;
    if (tid < 256) {
        v  = c[CAND2 - 1 - tid];
        ex = expf(key2f((unsigned)(v >> 32)) - smax);
        red[tid] = ex;
    }
    __syncthreads();
    for (int s = 128; s > 0; s >>= 1) {
        if (tid < s) red[tid] += red[tid + s];
        __syncthreads();
    }
    if (tid < 256) {
        float w = ex / red[0];
        if (tid >= bud) w = 0.f;
        g_topidx[(size_t)tok * KSEL + tid] = (int)(0xFFFFFFFFu - (unsigned)(v & 0xFFFFFFFFull));
        g_topw[(size_t)tok * KSEL + tid]   = w;
    }
}

// ---------------------------------------------------------------------------
// Kernel 5: executor
// ---------------------------------------------------------------------------
__global__ void executor_kernel(const float* __restrict__ x,
                                const float* __restrict__ pool,
                                float* __restrict__ out) {
    __shared__ float xs[DIM];
    __shared__ float partial[8][DIM];
    int tok  = blockIdx.x;
    int tid  = threadIdx.x;
    int warp = tid >> 5;
    int lane = tid & 31;

    for (int i = tid; i < DIM; i += 256) xs[i] = x[(size_t)tok * DIM + i];
    __syncthreads();

    float acc[16];
#pragma unroll
    for (int j = 0; j < 16; j++) acc[j] = 0.f;

    for (int k = warp; k < KSEL; k += 8) {
        float w = g_topw[(size_t)tok * KSEL + k];
        if (w != 0.f) {
            int idx = g_topidx[(size_t)tok * KSEL + k];
            const float* row = pool + (size_t)idx * DIM;
            float r[16];
            float p = 0.f;
#pragma unroll
            for (int j = 0; j < 16; j++) {
                r[j] = __ldg(row + lane + 32 * j);
                p += xs[lane + 32 * j] * r[j];
            }
#pragma unroll
            for (int off = 16; off > 0; off >>= 1)
                p += __shfl_xor_sync(0xffffffffu, p, off);
            float act = tanhf(p) * w;
#pragma unroll
            for (int j = 0; j < 16; j++) acc[j] += act * r[j];
        }
    }

#pragma unroll
    for (int j = 0; j < 16; j++) partial[warp][lane + 32 * j] = acc[j];
    __syncthreads();

    for (int e = tid; e < DIM; e += 256) {
        float s = xs[e];
#pragma unroll
        for (int wp = 0; wp < 8; wp++) s += partial[wp][e];
        out[(size_t)tok * DIM + e] = s;
    }
}

// ---------------------------------------------------------------------------
extern "C" void kernel_launch(void* const* d_in, const int* in_sizes, int n_in,
                              void* d_out, int out_size) {
    const float* x    = (const float*)d_in[0];
    const float* pool = (const float*)d_in[1];
    const float* Wc1  = (const float*)d_in[2];
    const float* bc1  = (const float*)d_in[3];
    const float* Wc2  = (const float*)d_in[4];
    const float* bc2  = (const float*)d_in[5];
    const float* Ws1  = (const float*)d_in[6];
    const float* bs1  = (const float*)d_in[7];
    const float* Ws2  = (const float*)d_in[8];
    const float* bs2  = (const float*)d_in[9];
    float* out = (float*)d_out;

    cudaFuncSetAttribute(gemm_kernel,
                         cudaFuncAttributeMaxDynamicSharedMemorySize,
                         GEMM_SMEM_BYTES);

    zero_kernel<<<(N_TOK + 511) / 512, 512>>>();
    budget_kernel<<<N_TOK / 16, 128>>>(x, Wc1, bc1, Wc2, bc2);
    hidden_kernel<<<N_TOK / 16, 256>>>(x, Ws1, bs1);
    floor_kernel<<<N_TOK / 8, 256>>>();

    dim3 ggrid(N_TOK / BM, POOLSZ / BN);   // x = m fast -> Ws2 slice reused in L2
    gemm_kernel<<<ggrid, 256, GEMM_SMEM_BYTES>>>(Ws2, bs2);

    fallback_kernel<<<N_TOK, 256>>>(Ws2, bs2);
    select_kernel<<<N_TOK, TPS>>>();

    executor_kernel<<<N_TOK, 256>>>(x, pool, out);
}

// round 10
// speedup vs baseline: 16.3985x; 16.3985x over previous
#include <cuda_runtime.h>
#include <math.h>
#include <stdint.h>

// Problem constants
#define N_TOK   2048
#define DIM     512
#define POOLSZ  65536
#define HIDDEN  256
#define CHID    128
#define KSEL    256
#define CAND2   2048        // candidate buffer depth per token
#define FLOORZ  2.4f        // floor = FLOORZ * sigma_token  (E[count]=537, sd=23)

// GEMM tiling
#define BM 128
#define BN 256
#define BK 32
#define SA (BM * 36)        // As stage stride (floats), pad 36 (frag bank = 4g+tg, injective)
#define SB (BK * 264)       // Bs stage stride (floats), pad 264 (frag bank = 8tg+g, injective)
#define GEMM_SMEM_FLOATS (2 * SA + 2 * SB + BN + BM)
#define GEMM_SMEM_BYTES  (GEMM_SMEM_FLOATS * 4)

// Device scratch
__device__ float              g_h[N_TOK * HIDDEN];
__device__ float              g_floor[N_TOK];
__device__ unsigned           g_ccnt[N_TOK];
__device__ unsigned long long g_cand[(size_t)N_TOK * CAND2];
__device__ int                g_budget[N_TOK];
__device__ int                g_topidx[N_TOK * KSEL];
__device__ float              g_topw[N_TOK * KSEL];

// key helpers: monotonic float->uint mapping
__device__ __forceinline__ unsigned f2key(float s) {
    unsigned u = __float_as_uint(s);
    return (u & 0x80000000u) ? ~u : (u | 0x80000000u);
}
__device__ __forceinline__ float key2f(unsigned k) {
    return (k & 0x80000000u) ? __uint_as_float(k ^ 0x80000000u)
                             : __uint_as_float(~k);
}
// pack: sort desc by key; ties -> smaller index first (matches jax top_k)
__device__ __forceinline__ unsigned long long packc(unsigned key, unsigned idx) {
    return ((unsigned long long)key << 32) | (unsigned long long)(0xFFFFFFFFu - idx);
}

__device__ __forceinline__ void cp_async16(uint32_t saddr, const void* gaddr) {
    asm volatile("cp.async.cg.shared.global [%0], [%1], 16;\n"
                 :: "r"(saddr), "l"(gaddr));
}
__device__ __forceinline__ void cp_commit() {
    asm volatile("cp.async.commit_group;\n");
}
template <int N> __device__ __forceinline__ void cp_wait() {
    asm volatile("cp.async.wait_group %0;\n" :: "n"(N));
}

__device__ __forceinline__ void mma_tf32(float* d, const uint32_t* a, const uint32_t* b) {
    asm volatile(
        "mma.sync.aligned.m16n8k8.row.col.f32.tf32.tf32.f32 "
        "{%0,%1,%2,%3}, {%4,%5,%6,%7}, {%8,%9}, {%0,%1,%2,%3};"
        : "+f"(d[0]), "+f"(d[1]), "+f"(d[2]), "+f"(d[3])
        : "r"(a[0]), "r"(a[1]), "r"(a[2]), "r"(a[3]), "r"(b[0]), "r"(b[1]));
}

// ---------------------------------------------------------------------------
// zero candidate counters (graph-replay safe)
// ---------------------------------------------------------------------------
__global__ void zero_kernel() {
    int i = blockIdx.x * blockDim.x + threadIdx.x;
    if (i < N_TOK) g_ccnt[i] = 0;
}

// ---------------------------------------------------------------------------
// Kernel 1: complexity net -> budget[token]
// ---------------------------------------------------------------------------
__global__ void budget_kernel(const float* __restrict__ x,
                              const float* __restrict__ Wc1,
                              const float* __restrict__ bc1,
                              const float* __restrict__ Wc2,
                              const float* __restrict__ bc2) {
    __shared__ float xs[16][DIM];
    __shared__ float red[16][CHID];
    int tid = threadIdx.x;            // 0..127
    int t0  = blockIdx.x * 16;

    const float4* xsrc = (const float4*)(x + (size_t)t0 * DIM);
    float4* xdst = (float4*)&xs[0][0];
    for (int i = tid; i < 16 * DIM / 4; i += 128) xdst[i] = xsrc[i];
    __syncthreads();

    float acc[16];
#pragma unroll
    for (int m = 0; m < 16; m++) acc[m] = 0.f;

    for (int i = 0; i < DIM; i += 4) {
        float w0 = Wc1[(i + 0) * CHID + tid];
        float w1 = Wc1[(i + 1) * CHID + tid];
        float w2 = Wc1[(i + 2) * CHID + tid];
        float w3 = Wc1[(i + 3) * CHID + tid];
#pragma unroll
        for (int m = 0; m < 16; m++) {
            float4 xv = *(const float4*)&xs[m][i];
            acc[m] += xv.x * w0 + xv.y * w1 + xv.z * w2 + xv.w * w3;
        }
    }

    float b1  = bc1[tid];
    float wc2 = Wc2[tid];
#pragma unroll
    for (int m = 0; m < 16; m++) red[m][tid] = fmaxf(acc[m] + b1, 0.f) * wc2;
    __syncthreads();

    if (tid < 16) {
        float s = bc2[0];
        for (int t = 0; t < CHID; t++) s += red[tid][t];
        float sig   = 1.f / (1.f + expf(-s));
        float scale = sig * sig;
        float raw   = 100.f + 156.f * scale;
        raw = fminf(fmaxf(raw, 100.f), 256.f);
        g_budget[t0 + tid] = (int)rintf(raw);
    }
}

// ---------------------------------------------------------------------------
// Kernel 2: scorer hidden h = relu(x @ Ws1 + bs1)
// ---------------------------------------------------------------------------
__global__ void hidden_kernel(const float* __restrict__ x,
                              const float* __restrict__ Ws1,
                              const float* __restrict__ bs1) {
    __shared__ float xs[16][DIM];
    int tid = threadIdx.x;            // 0..255
    int t0  = blockIdx.x * 16;

    const float4* xsrc = (const float4*)(x + (size_t)t0 * DIM);
    float4* xdst = (float4*)&xs[0][0];
    for (int i = tid; i < 16 * DIM / 4; i += 256) xdst[i] = xsrc[i];
    __syncthreads();

    float acc[16];
#pragma unroll
    for (int m = 0; m < 16; m++) acc[m] = 0.f;

    for (int i = 0; i < DIM; i += 4) {
        float w0 = Ws1[(i + 0) * HIDDEN + tid];
        float w1 = Ws1[(i + 1) * HIDDEN + tid];
        float w2 = Ws1[(i + 2) * HIDDEN + tid];
        float w3 = Ws1[(i + 3) * HIDDEN + tid];
#pragma unroll
        for (int m = 0; m < 16; m++) {
            float4 xv = *(const float4*)&xs[m][i];
            acc[m] += xv.x * w0 + xv.y * w1 + xv.z * w2 + xv.w * w3;
        }
    }

    float b = bs1[tid];
#pragma unroll
    for (int m = 0; m < 16; m++)
        g_h[(size_t)(t0 + m) * HIDDEN + tid] = fmaxf(acc[m] + b, 0.f);
}

// ---------------------------------------------------------------------------
// Kernel 2b: per-token candidate floor = FLOORZ * ||h|| / 16
// (score | h  is exactly N(bias, ||h||^2/256) for i.i.d. normal Ws2 columns)
// ---------------------------------------------------------------------------
__global__ void floor_kernel() {
    int tok  = blockIdx.x * 8 + (threadIdx.x >> 5);
    int lane = threadIdx.x & 31;
    const float* h = g_h + (size_t)tok * HIDDEN;
    float s = 0.f;
    for (int i = lane; i < HIDDEN; i += 32) { float v = h[i]; s += v * v; }
#pragma unroll
    for (int off = 16; off > 0; off >>= 1)
        s += __shfl_xor_sync(0xffffffffu, s, off);
    if (lane == 0) g_floor[tok] = FLOORZ * sqrtf(s) * (1.0f / 16.0f);
}

// ---------------------------------------------------------------------------
// Kernel 3: tf32 tensor-core GEMM with fused candidate filter.
// CTA 128x256, BK=32, 8 warps (2m x 4n), warp tile 64x64,
// cp.async double-buffered stages, fp32 bits fed to tf32 MMA (HW truncation).
// Epilogue: score >= floor[token] -> push packed candidate; no score store.
// ---------------------------------------------------------------------------
__global__ __launch_bounds__(256, 1) void gemm_kernel(const float* __restrict__ Ws2,
                                                      const float* __restrict__ bs2) {
    extern __shared__ float smem[];
    float* bias_s  = smem + 2 * SA + 2 * SB;
    float* floor_s = bias_s + BN;

    int tid  = threadIdx.x;
    int warp = tid >> 5, lane = tid & 31;
    int wm = warp >> 2, wn = warp & 3;     // 2 x 4 warps
    int g  = lane >> 2, tg = lane & 3;
    int m0 = blockIdx.x * BM;
    int n0 = blockIdx.y * BN;

    for (int i = tid; i < BN; i += 256) bias_s[i]  = bs2[n0 + i];
    for (int i = tid; i < BM; i += 256) floor_s[i] = g_floor[m0 + i];

    uint32_t sbase = (uint32_t)__cvta_generic_to_shared(smem);
    const float* gA = g_h + (size_t)m0 * HIDDEN;
    const float* gB = Ws2 + n0;

    int arow = tid >> 3;                   // A: rows arow + {0,32,64,96}
    int ak4  = (tid & 7) << 2;

    // prologue: stage 0
#pragma unroll
    for (int i = 0; i < 4; i++) {
        int row = arow + i * 32;
        cp_async16(sbase + (uint32_t)((row * 36 + ak4) * 4),
                   gA + (size_t)row * HIDDEN + ak4);
    }
#pragma unroll
    for (int i = 0; i < 8; i++) {          // 2048 float4 = full 32x256 tile
        int s  = tid + i * 256;
        int k  = s >> 6;                   // 64 float4 per k-row
        int n4 = (s & 63) << 2;
        cp_async16(sbase + (uint32_t)((2 * SA + k * 264 + n4) * 4),
                   gB + (size_t)k * POOLSZ + n4);
    }
    cp_commit();

    float acc[4][8][4];
#pragma unroll
    for (int mt = 0; mt < 4; mt++)
#pragma unroll
        for (int nt = 0; nt < 8; nt++)
#pragma unroll
            for (int c = 0; c < 4; c++) acc[mt][nt][c] = 0.f;

    for (int it = 0; it < HIDDEN / BK; it++) {
        int buf = it & 1;
        if (it < HIDDEN / BK - 1) {
            int kb   = (it + 1) * BK;
            int nbuf = buf ^ 1;
#pragma unroll
            for (int i = 0; i < 4; i++) {
                int row = arow + i * 32;
                cp_async16(sbase + (uint32_t)((nbuf * SA + row * 36 + ak4) * 4),
                           gA + (size_t)row * HIDDEN + kb + ak4);
            }
#pragma unroll
            for (int i = 0; i < 8; i++) {
                int s  = tid + i * 256;
                int k  = s >> 6;
                int n4 = (s & 63) << 2;
                cp_async16(sbase + (uint32_t)((2 * SA + nbuf * SB + k * 264 + n4) * 4),
                           gB + (size_t)(kb + k) * POOLSZ + n4);
            }
            cp_commit();
            cp_wait<1>();
        } else {
            cp_wait<0>();
        }
        __syncthreads();

        const float* Ab = smem + buf * SA;
        const float* Bb = smem + 2 * SA + buf * SB;

#pragma unroll
        for (int kk = 0; kk < BK; kk += 8) {
            uint32_t af[4][4];
#pragma unroll
            for (int mt = 0; mt < 4; mt++) {
                int mm = wm * 64 + mt * 16;
                af[mt][0] = __float_as_uint(Ab[(mm + g) * 36 + kk + tg]);
                af[mt][1] = __float_as_uint(Ab[(mm + g + 8) * 36 + kk + tg]);
                af[mt][2] = __float_as_uint(Ab[(mm + g) * 36 + kk + tg + 4]);
                af[mt][3] = __float_as_uint(Ab[(mm + g + 8) * 36 + kk + tg + 4]);
            }
            uint32_t bf[8][2];
#pragma unroll
            for (int nt = 0; nt < 8; nt++) {
                int nn = wn * 64 + nt * 8;
                bf[nt][0] = __float_as_uint(Bb[(kk + tg) * 264 + nn + g]);
                bf[nt][1] = __float_as_uint(Bb[(kk + tg + 4) * 264 + nn + g]);
            }
#pragma unroll
            for (int mt = 0; mt < 4; mt++)
#pragma unroll
                for (int nt = 0; nt < 8; nt++)
                    mma_tf32(acc[mt][nt], af[mt], bf[nt]);
        }
        __syncthreads();
    }

    // epilogue: bias + candidate filter (no score store)
#pragma unroll
    for (int mt = 0; mt < 4; mt++) {
#pragma unroll
        for (int c = 0; c < 4; c++) {
            int m_loc = wm * 64 + mt * 16 + g + ((c & 2) ? 8 : 0);
            float flo = floor_s[m_loc];
            int m = m0 + m_loc;
#pragma unroll
            for (int nt = 0; nt < 8; nt++) {
                int n_loc = wn * 64 + nt * 8 + 2 * tg + (c & 1);
                float s = acc[mt][nt][c] + bias_s[n_loc];
                if (s >= flo) {
                    unsigned pos = atomicAdd(&g_ccnt[m], 1u);
                    if (pos < CAND2)
                        g_cand[(size_t)m * CAND2 + pos] =
                            packc(f2key(s), (unsigned)(n0 + n_loc));
                }
            }
        }
    }
}

// ---------------------------------------------------------------------------
// Kernel 3b: fallback for tokens whose candidate count is out of range.
// Recomputes the full score row (fp32) + exact 13-bit histogram select,
// rewrites the candidate buffer. Early-exits in the normal case.
// ---------------------------------------------------------------------------
#define HB 8192
__global__ void fallback_kernel(const float* __restrict__ Ws2,
                                const float* __restrict__ bs2) {
    int tok = blockIdx.x;
    unsigned cnt0 = g_ccnt[tok];
    if (cnt0 >= KSEL && cnt0 <= CAND2) return;

    __shared__ float    hs[HIDDEN];
    __shared__ unsigned hist[HB];
    __shared__ unsigned bsum[256];
    __shared__ unsigned s_thresh, s_cnt;
    int tid = threadIdx.x;            // 0..255

    for (int i = tid; i < HIDDEN; i += 256) hs[i] = g_h[(size_t)tok * HIDDEN + i];
    for (int i = tid; i < HB; i += 256) hist[i] = 0;
    if (tid == 0) s_cnt = 0;
    __syncthreads();

    // pass 1: histogram of recomputed scores
    for (int j0 = 0; j0 < POOLSZ; j0 += 256) {
        int j = j0 + tid;
        float s = bs2[j];
        for (int k = 0; k < HIDDEN; k += 4) {
            float4 hv = *(const float4*)&hs[k];
            s += hv.x * Ws2[(size_t)(k + 0) * POOLSZ + j];
            s += hv.y * Ws2[(size_t)(k + 1) * POOLSZ + j];
            s += hv.z * Ws2[(size_t)(k + 2) * POOLSZ + j];
            s += hv.w * Ws2[(size_t)(k + 3) * POOLSZ + j];
        }
        atomicAdd(&hist[f2key(s) >> 19], 1u);
    }
    __syncthreads();

    unsigned local = 0;
    int base = tid * 32;
#pragma unroll
    for (int b = 0; b < 32; b++) local += hist[base + b];
    bsum[tid] = local;
    __syncthreads();
    if (tid == 0) {
        unsigned cum = 0;
        int blk = 255;
        for (; blk > 0; blk--) {
            if (cum + bsum[blk] >= KSEL) break;
            cum += bsum[blk];
        }
        int b = blk * 32 + 31;
        for (;; b--) {
            unsigned c = hist[b];
            if (cum + c >= KSEL || b == 0) break;
            cum += c;
        }
        s_thresh = (unsigned)b << 19;
    }
    __syncthreads();
    unsigned th = s_thresh;

    // pass 2: recompute + collect
    for (int j0 = 0; j0 < POOLSZ; j0 += 256) {
        int j = j0 + tid;
        float s = bs2[j];
        for (int k = 0; k < HIDDEN; k += 4) {
            float4 hv = *(const float4*)&hs[k];
            s += hv.x * Ws2[(size_t)(k + 0) * POOLSZ + j];
            s += hv.y * Ws2[(size_t)(k + 1) * POOLSZ + j];
            s += hv.z * Ws2[(size_t)(k + 2) * POOLSZ + j];
            s += hv.w * Ws2[(size_t)(k + 3) * POOLSZ + j];
        }
        unsigned key = f2key(s);
        if (key >= th) {
            unsigned pos = atomicAdd(&s_cnt, 1u);
            if (pos < CAND2)
                g_cand[(size_t)tok * CAND2 + pos] = packc(key, (unsigned)j);
        }
    }
    __syncthreads();
    if (tid == 0) {
        unsigned c = s_cnt;
        g_ccnt[tok] = (c > CAND2) ? CAND2 : c;
    }
}

// ---------------------------------------------------------------------------
// Kernel 4: per-token select: bitonic sort of <=2048 packed candidates,
// softmax over top-256, budget mask.
// ---------------------------------------------------------------------------
#define TPS 512
__global__ void select_kernel() {
    __shared__ unsigned long long c[CAND2];   // 16 KB
    __shared__ float red[256];
    int tid = threadIdx.x;                    // 0..511
    int tok = blockIdx.x;

    unsigned cnt = g_ccnt[tok];
    if (cnt > CAND2) cnt = CAND2;
    for (int i = tid; i < CAND2; i += TPS)
        c[i] = (i < (int)cnt) ? g_cand[(size_t)tok * CAND2 + i] : 0ULL;
    __syncthreads();

    // bitonic sort ascending (largest at CAND2-1)
    for (unsigned k = 2; k <= CAND2; k <<= 1) {
        for (unsigned j = k >> 1; j > 0; j >>= 1) {
            for (unsigned i = tid; i < CAND2; i += TPS) {
                unsigned ixj = i ^ j;
                if (ixj > i) {
                    bool up = ((i & k) == 0);
                    unsigned long long a = c[i], b = c[ixj];
                    if (up ? (a > b) : (a < b)) { c[i] = b; c[ixj] = a; }
                }
            }
            __syncthreads();
        }
    }

    int bud = g_budget[tok];
    float smax = key2f((unsigned)(c[CAND2 - 1] >> 32));
    float ex = 0.f;
    unsigned long long v = 0ULL;
    if (tid < 256) {
        v  = c[CAND2 - 1 - tid];
        ex = expf(key2f((unsigned)(v >> 32)) - smax);
        red[tid] = ex;
    }
    __syncthreads();
    for (int s = 128; s > 0; s >>= 1) {
        if (tid < s) red[tid] += red[tid + s];
        __syncthreads();
    }
    if (tid < 256) {
        float w = ex / red[0];
        if (tid >= bud) w = 0.f;
        g_topidx[(size_t)tok * KSEL + tid] = (int)(0xFFFFFFFFu - (unsigned)(v & 0xFFFFFFFFull));
        g_topw[(size_t)tok * KSEL + tid]   = w;
    }
}

// ---------------------------------------------------------------------------
// Kernel 5: executor
// ---------------------------------------------------------------------------
__global__ void executor_kernel(const float* __restrict__ x,
                                const float* __restrict__ pool,
                                float* __restrict__ out) {
    __shared__ float xs[DIM];
    __shared__ float partial[8][DIM];
    int tok  = blockIdx.x;
    int tid  = threadIdx.x;
    int warp = tid >> 5;
    int lane = tid & 31;

    for (int i = tid; i < DIM; i += 256) xs[i] = x[(size_t)tok * DIM + i];
    __syncthreads();

    float acc[16];
#pragma unroll
    for (int j = 0; j < 16; j++) acc[j] = 0.f;

    for (int k = warp; k < KSEL; k += 8) {
        float w = g_topw[(size_t)tok * KSEL + k];
        if (w != 0.f) {
            int idx = g_topidx[(size_t)tok * KSEL + k];
            const float* row = pool + (size_t)idx * DIM;
            float r[16];
            float p = 0.f;
#pragma unroll
            for (int j = 0; j < 16; j++) {
                r[j] = __ldg(row + lane + 32 * j);
                p += xs[lane + 32 * j] * r[j];
            }
#pragma unroll
            for (int off = 16; off > 0; off >>= 1)
                p += __shfl_xor_sync(0xffffffffu, p, off);
            float act = tanhf(p) * w;
#pragma unroll
            for (int j = 0; j < 16; j++) acc[j] += act * r[j];
        }
    }

#pragma unroll
    for (int j = 0; j < 16; j++) partial[warp][lane + 32 * j] = acc[j];
    __syncthreads();

    for (int e = tid; e < DIM; e += 256) {
        float s = xs[e];
#pragma unroll
        for (int wp = 0; wp < 8; wp++) s += partial[wp][e];
        out[(size_t)tok * DIM + e] = s;
    }
}

// ---------------------------------------------------------------------------
extern "C" void kernel_launch(void* const* d_in, const int* in_sizes, int n_in,
                              void* d_out, int out_size) {
    const float* x    = (const float*)d_in[0];
    const float* pool = (const float*)d_in[1];
    const float* Wc1  = (const float*)d_in[2];
    const float* bc1  = (const float*)d_in[3];
    const float* Wc2  = (const float*)d_in[4];
    const float* bc2  = (const float*)d_in[5];
    const float* Ws1  = (const float*)d_in[6];
    const float* bs1  = (const float*)d_in[7];
    const float* Ws2  = (const float*)d_in[8];
    const float* bs2  = (const float*)d_in[9];
    float* out = (float*)d_out;

    cudaFuncSetAttribute(gemm_kernel,
                         cudaFuncAttributeMaxDynamicSharedMemorySize,
                         GEMM_SMEM_BYTES);

    zero_kernel<<<(N_TOK + 511) / 512, 512>>>();
    budget_kernel<<<N_TOK / 16, 128>>>(x, Wc1, bc1, Wc2, bc2);
    hidden_kernel<<<N_TOK / 16, 256>>>(x, Ws1, bs1);
    floor_kernel<<<N_TOK / 8, 256>>>();

    dim3 ggrid(N_TOK / BM, POOLSZ / BN);   // x = m fast -> Ws2 slice reused in L2
    gemm_kernel<<<ggrid, 256, GEMM_SMEM_BYTES>>>(Ws2, bs2);

    fallback_kernel<<<N_TOK, 256>>>(Ws2, bs2);
    select_kernel<<<N_TOK, TPS>>>();

    executor_kernel<<<N_TOK, 256>>>(x, pool, out);
}

// round 11
// speedup vs baseline: 26.5115x; 1.6167x over previous
#include <cuda_runtime.h>
#include <cuda_bf16.h>
#include <math.h>
#include <stdint.h>

// Problem constants
#define N_TOK   2048
#define DIM     512
#define POOLSZ  65536
#define HIDDEN  256
#define HID2    128         // HIDDEN/2 (bf16 pair words)
#define CHID    128
#define KSEL    256
#define CAND2   1024        // candidate buffer depth per token
#define FLOORZ  2.4f        // floor = FLOORZ*sigma  (E[count]=537, sd=23, cap 1024 = 21 sd)

// GEMM tiling (bf16 mma.sync m16n8k16)
#define BM 128
#define BN 128
#define BK2 32              // k-pair words per stage (= 64 bf16 k)
#define SAW (BM * 36)       // A stage words, row stride 36 (frag bank 4g+tg injective)
#define SBW (BK2 * 136)     // B stage words, row stride 136 (frag bank 8tg+g injective)
#define GEMM_SMEM_WORDS (2 * SAW + 2 * SBW + BN + BM)
#define GEMM_SMEM_BYTES (GEMM_SMEM_WORDS * 4)

// Device scratch
__device__ float              g_h[N_TOK * HIDDEN];                 // fp32 hidden (floor, fallback)
__device__ unsigned           g_hb[N_TOK * HID2];                  // bf16x2 hidden
__device__ unsigned           g_w2i[(size_t)HID2 * POOLSZ];        // bf16x2 Ws2, pair-interleaved (32 MB)
__device__ float              g_floor[N_TOK];
__device__ unsigned           g_ccnt[N_TOK];
__device__ unsigned long long g_cand[(size_t)N_TOK * CAND2];
__device__ int                g_budget[N_TOK];
__device__ int                g_topidx[N_TOK * KSEL];
__device__ float              g_topw[N_TOK * KSEL];

// key helpers: monotonic float->uint mapping
__device__ __forceinline__ unsigned f2key(float s) {
    unsigned u = __float_as_uint(s);
    return (u & 0x80000000u) ? ~u : (u | 0x80000000u);
}
__device__ __forceinline__ float key2f(unsigned k) {
    return (k & 0x80000000u) ? __uint_as_float(k ^ 0x80000000u)
                             : __uint_as_float(~k);
}
// pack: sort desc by key; ties -> smaller index first (matches jax top_k)
__device__ __forceinline__ unsigned long long packc(unsigned key, unsigned idx) {
    return ((unsigned long long)key << 32) | (unsigned long long)(0xFFFFFFFFu - idx);
}
// pack two floats to bf16x2 word (lo = even-k element)
__device__ __forceinline__ unsigned packbf(float lo, float hi) {
    __nv_bfloat162 t;
    t.x = __float2bfloat16(lo);
    t.y = __float2bfloat16(hi);
    return *(unsigned*)&t;
}

__device__ __forceinline__ void cp_async16(uint32_t saddr, const void* gaddr) {
    asm volatile("cp.async.cg.shared.global [%0], [%1], 16;\n"
                 :: "r"(saddr), "l"(gaddr));
}
__device__ __forceinline__ void cp_commit() {
    asm volatile("cp.async.commit_group;\n");
}
template <int N> __device__ __forceinline__ void cp_wait() {
    asm volatile("cp.async.wait_group %0;\n" :: "n"(N));
}

__device__ __forceinline__ void mma_bf16(float* d, const uint32_t* a, const uint32_t* b) {
    asm volatile(
        "mma.sync.aligned.m16n8k16.row.col.f32.bf16.bf16.f32 "
        "{%0,%1,%2,%3}, {%4,%5,%6,%7}, {%8,%9}, {%0,%1,%2,%3};"
        : "+f"(d[0]), "+f"(d[1]), "+f"(d[2]), "+f"(d[3])
        : "r"(a[0]), "r"(a[1]), "r"(a[2]), "r"(a[3]), "r"(b[0]), "r"(b[1]));
}

// ---------------------------------------------------------------------------
// Kernel 0: convert Ws2 fp32 [HIDDEN][POOLSZ] -> bf16 pair-interleaved words
// g_w2i[k2][n] = {bf16(Ws2[2k2][n]), bf16(Ws2[2k2+1][n])}
// ---------------------------------------------------------------------------
__global__ void w2conv_kernel(const float* __restrict__ Ws2) {
    int n  = blockIdx.x * 256 + threadIdx.x;
    int k2 = blockIdx.y;
    float a = Ws2[(size_t)(2 * k2) * POOLSZ + n];
    float b = Ws2[(size_t)(2 * k2 + 1) * POOLSZ + n];
    g_w2i[(size_t)k2 * POOLSZ + n] = packbf(a, b);
}

// ---------------------------------------------------------------------------
// Kernel 1: complexity net -> budget[token]
// ---------------------------------------------------------------------------
__global__ void budget_kernel(const float* __restrict__ x,
                              const float* __restrict__ Wc1,
                              const float* __restrict__ bc1,
                              const float* __restrict__ Wc2,
                              const float* __restrict__ bc2) {
    __shared__ float xs[16][DIM];
    __shared__ float red[16][CHID];
    int tid = threadIdx.x;            // 0..127
    int t0  = blockIdx.x * 16;

    const float4* xsrc = (const float4*)(x + (size_t)t0 * DIM);
    float4* xdst = (float4*)&xs[0][0];
    for (int i = tid; i < 16 * DIM / 4; i += 128) xdst[i] = xsrc[i];
    __syncthreads();

    float acc[16];
#pragma unroll
    for (int m = 0; m < 16; m++) acc[m] = 0.f;

    for (int i = 0; i < DIM; i += 4) {
        float w0 = Wc1[(i + 0) * CHID + tid];
        float w1 = Wc1[(i + 1) * CHID + tid];
        float w2 = Wc1[(i + 2) * CHID + tid];
        float w3 = Wc1[(i + 3) * CHID + tid];
#pragma unroll
        for (int m = 0; m < 16; m++) {
            float4 xv = *(const float4*)&xs[m][i];
            acc[m] += xv.x * w0 + xv.y * w1 + xv.z * w2 + xv.w * w3;
        }
    }

    float b1  = bc1[tid];
    float wc2 = Wc2[tid];
#pragma unroll
    for (int m = 0; m < 16; m++) red[m][tid] = fmaxf(acc[m] + b1, 0.f) * wc2;
    __syncthreads();

    if (tid < 16) {
        float s = bc2[0];
        for (int t = 0; t < CHID; t++) s += red[tid][t];
        float sig   = 1.f / (1.f + expf(-s));
        float scale = sig * sig;
        float raw   = 100.f + 156.f * scale;
        raw = fminf(fmaxf(raw, 100.f), 256.f);
        g_budget[t0 + tid] = (int)rintf(raw);
    }
}

// ---------------------------------------------------------------------------
// Kernel 2: scorer hidden h = relu(x @ Ws1 + bs1); stores fp32 + bf16x2
// ---------------------------------------------------------------------------
__global__ void hidden_kernel(const float* __restrict__ x,
                              const float* __restrict__ Ws1,
                              const float* __restrict__ bs1) {
    __shared__ float xs[16][DIM];
    int tid = threadIdx.x;            // 0..255 (= hidden unit)
    int t0  = blockIdx.x * 16;

    const float4* xsrc = (const float4*)(x + (size_t)t0 * DIM);
    float4* xdst = (float4*)&xs[0][0];
    for (int i = tid; i < 16 * DIM / 4; i += 256) xdst[i] = xsrc[i];
    __syncthreads();

    float acc[16];
#pragma unroll
    for (int m = 0; m < 16; m++) acc[m] = 0.f;

    for (int i = 0; i < DIM; i += 4) {
        float w0 = Ws1[(i + 0) * HIDDEN + tid];
        float w1 = Ws1[(i + 1) * HIDDEN + tid];
        float w2 = Ws1[(i + 2) * HIDDEN + tid];
        float w3 = Ws1[(i + 3) * HIDDEN + tid];
#pragma unroll
        for (int m = 0; m < 16; m++) {
            float4 xv = *(const float4*)&xs[m][i];
            acc[m] += xv.x * w0 + xv.y * w1 + xv.z * w2 + xv.w * w3;
        }
    }

    float b = bs1[tid];
#pragma unroll
    for (int m = 0; m < 16; m++) {
        float hv = fmaxf(acc[m] + b, 0.f);
        g_h[(size_t)(t0 + m) * HIDDEN + tid] = hv;
        float other = __shfl_xor_sync(0xffffffffu, hv, 1);
        if ((tid & 1) == 0)
            g_hb[(size_t)(t0 + m) * HID2 + (tid >> 1)] = packbf(hv, other);
    }
}

// ---------------------------------------------------------------------------
// Kernel 2b: per-token floor = FLOORZ * ||h|| / 16; zero candidate counter
// ---------------------------------------------------------------------------
__global__ void floor_kernel() {
    int tok  = blockIdx.x * 8 + (threadIdx.x >> 5);
    int lane = threadIdx.x & 31;
    const float* h = g_h + (size_t)tok * HIDDEN;
    float s = 0.f;
    for (int i = lane; i < HIDDEN; i += 32) { float v = h[i]; s += v * v; }
#pragma unroll
    for (int off = 16; off > 0; off >>= 1)
        s += __shfl_xor_sync(0xffffffffu, s, off);
    if (lane == 0) {
        g_floor[tok] = FLOORZ * sqrtf(s) * (1.0f / 16.0f);
        g_ccnt[tok]  = 0;
    }
}

// ---------------------------------------------------------------------------
// Kernel 3: bf16 tensor-core GEMM with fused candidate filter.
// CTA 128x128, BK=64 (32 pair-words), 8 warps (2m x 4n), warp tile 64x32,
// mma.sync.m16n8k16.bf16, cp.async double buffered, 2 CTAs/SM.
// Epilogue: score >= floor[token] -> push packed candidate; no score store.
// ---------------------------------------------------------------------------
__global__ __launch_bounds__(256, 2) void gemm_kernel(const float* __restrict__ bs2) {
    extern __shared__ unsigned smem[];             // word-addressed
    float* bias_s  = (float*)(smem + 2 * SAW + 2 * SBW);
    float* floor_s = bias_s + BN;

    int tid  = threadIdx.x;
    int warp = tid >> 5, lane = tid & 31;
    int wm = warp >> 2, wn = warp & 3;             // 2 x 4 warps
    int g  = lane >> 2, tg = lane & 3;
    int m0 = blockIdx.x * BM;
    int n0 = blockIdx.y * BN;

    for (int i = tid; i < BN; i += 256) bias_s[i]  = bs2[n0 + i];
    for (int i = tid; i < BM; i += 256) floor_s[i] = g_floor[m0 + i];

    uint32_t sbase = (uint32_t)__cvta_generic_to_shared(smem);
    const unsigned* gA = g_hb + (size_t)m0 * HID2;
    const unsigned* gB = g_w2i + n0;

    // staging decompositions (1024 float4 slots each, 4 iters of 256 threads)
    // A: row = s>>3 (128 rows), quad = (s&7)*4  (32 words/row)
    // B: k2  = s>>5 (32 rows),  quad = (s&31)*4 (128 words/row)

    // prologue: stage 0 (kb2 = 0)
#pragma unroll
    for (int i = 0; i < 4; i++) {
        int s = tid + i * 256;
        int row = s >> 3, q = (s & 7) << 2;
        cp_async16(sbase + (uint32_t)((row * 36 + q) * 4),
                   gA + (size_t)row * HID2 + q);
    }
#pragma unroll
    for (int i = 0; i < 4; i++) {
        int s = tid + i * 256;
        int k2 = s >> 5, q = (s & 31) << 2;
        cp_async16(sbase + (uint32_t)((2 * SAW + k2 * 136 + q) * 4),
                   gB + (size_t)k2 * POOLSZ + q);
    }
    cp_commit();

    float acc[4][4][4];
#pragma unroll
    for (int mt = 0; mt < 4; mt++)
#pragma unroll
        for (int nt = 0; nt < 4; nt++)
#pragma unroll
            for (int c = 0; c < 4; c++) acc[mt][nt][c] = 0.f;

    for (int it = 0; it < HID2 / BK2; it++) {      // 4 stages
        int buf = it & 1;
        if (it < HID2 / BK2 - 1) {
            int kb2  = (it + 1) * BK2;
            int nbuf = buf ^ 1;
#pragma unroll
            for (int i = 0; i < 4; i++) {
                int s = tid + i * 256;
                int row = s >> 3, q = (s & 7) << 2;
                cp_async16(sbase + (uint32_t)((nbuf * SAW + row * 36 + q) * 4),
                           gA + (size_t)row * HID2 + kb2 + q);
            }
#pragma unroll
            for (int i = 0; i < 4; i++) {
                int s = tid + i * 256;
                int k2 = s >> 5, q = (s & 31) << 2;
                cp_async16(sbase + (uint32_t)((2 * SAW + nbuf * SBW + k2 * 136 + q) * 4),
                           gB + (size_t)(kb2 + k2) * POOLSZ + q);
            }
            cp_commit();
            cp_wait<1>();
        } else {
            cp_wait<0>();
        }
        __syncthreads();

        const unsigned* Ab = smem + buf * SAW;
        const unsigned* Bb = smem + 2 * SAW + buf * SBW;

#pragma unroll
        for (int kk = 0; kk < 4; kk++) {           // 4 k16 steps per stage
            uint32_t af[4][4];
#pragma unroll
            for (int mt = 0; mt < 4; mt++) {
                int mm = wm * 64 + mt * 16;
                af[mt][0] = Ab[(mm + g) * 36 + kk * 8 + tg];
                af[mt][1] = Ab[(mm + g + 8) * 36 + kk * 8 + tg];
                af[mt][2] = Ab[(mm + g) * 36 + kk * 8 + tg + 4];
                af[mt][3] = Ab[(mm + g + 8) * 36 + kk * 8 + tg + 4];
            }
            uint32_t bf[4][2];
#pragma unroll
            for (int nt = 0; nt < 4; nt++) {
                int nn = wn * 32 + nt * 8;
                bf[nt][0] = Bb[(kk * 8 + tg) * 136 + nn + g];
                bf[nt][1] = Bb[(kk * 8 + tg + 4) * 136 + nn + g];
            }
#pragma unroll
            for (int mt = 0; mt < 4; mt++)
#pragma unroll
                for (int nt = 0; nt < 4; nt++)
                    mma_bf16(acc[mt][nt], af[mt], bf[nt]);
        }
        __syncthreads();
    }

    // epilogue: bias + candidate filter (no score store)
#pragma unroll
    for (int mt = 0; mt < 4; mt++) {
#pragma unroll
        for (int c = 0; c < 4; c++) {
            int m_loc = wm * 64 + mt * 16 + g + ((c & 2) ? 8 : 0);
            float flo = floor_s[m_loc];
            int m = m0 + m_loc;
#pragma unroll
            for (int nt = 0; nt < 4; nt++) {
                int n_loc = wn * 32 + nt * 8 + 2 * tg + (c & 1);
                float s = acc[mt][nt][c] + bias_s[n_loc];
                if (s >= flo) {
                    unsigned pos = atomicAdd(&g_ccnt[m], 1u);
                    if (pos < CAND2)
                        g_cand[(size_t)m * CAND2 + pos] =
                            packc(f2key(s), (unsigned)(n0 + n_loc));
                }
            }
        }
    }
}

// ---------------------------------------------------------------------------
// Kernel 3b: fallback for tokens whose candidate count is out of range.
// Recomputes the full score row (fp32) + exact 13-bit histogram select.
// Early-exits in the normal case.
// ---------------------------------------------------------------------------
#define HB 8192
__global__ void fallback_kernel(const float* __restrict__ Ws2,
                                const float* __restrict__ bs2) {
    int tok = blockIdx.x;
    unsigned cnt0 = g_ccnt[tok];
    if (cnt0 >= KSEL && cnt0 <= CAND2) return;

    __shared__ float    hs[HIDDEN];
    __shared__ unsigned hist[HB];
    __shared__ unsigned bsum[256];
    __shared__ unsigned s_thresh, s_cnt;
    int tid = threadIdx.x;            // 0..255

    for (int i = tid; i < HIDDEN; i += 256) hs[i] = g_h[(size_t)tok * HIDDEN + i];
    for (int i = tid; i < HB; i += 256) hist[i] = 0;
    if (tid == 0) s_cnt = 0;
    __syncthreads();

    for (int j0 = 0; j0 < POOLSZ; j0 += 256) {
        int j = j0 + tid;
        float s = bs2[j];
        for (int k = 0; k < HIDDEN; k += 4) {
            float4 hv = *(const float4*)&hs[k];
            s += hv.x * Ws2[(size_t)(k + 0) * POOLSZ + j];
            s += hv.y * Ws2[(size_t)(k + 1) * POOLSZ + j];
            s += hv.z * Ws2[(size_t)(k + 2) * POOLSZ + j];
            s += hv.w * Ws2[(size_t)(k + 3) * POOLSZ + j];
        }
        atomicAdd(&hist[f2key(s) >> 19], 1u);
    }
    __syncthreads();

    unsigned local = 0;
    int base = tid * 32;
#pragma unroll
    for (int b = 0; b < 32; b++) local += hist[base + b];
    bsum[tid] = local;
    __syncthreads();
    if (tid == 0) {
        unsigned cum = 0;
        int blk = 255;
        for (; blk > 0; blk--) {
            if (cum + bsum[blk] >= KSEL) break;
            cum += bsum[blk];
        }
        int b = blk * 32 + 31;
        for (;; b--) {
            unsigned c = hist[b];
            if (cum + c >= KSEL || b == 0) break;
            cum += c;
        }
        s_thresh = (unsigned)b << 19;
    }
    __syncthreads();
    unsigned th = s_thresh;

    for (int j0 = 0; j0 < POOLSZ; j0 += 256) {
        int j = j0 + tid;
        float s = bs2[j];
        for (int k = 0; k < HIDDEN; k += 4) {
            float4 hv = *(const float4*)&hs[k];
            s += hv.x * Ws2[(size_t)(k + 0) * POOLSZ + j];
            s += hv.y * Ws2[(size_t)(k + 1) * POOLSZ + j];
            s += hv.z * Ws2[(size_t)(k + 2) * POOLSZ + j];
            s += hv.w * Ws2[(size_t)(k + 3) * POOLSZ + j];
        }
        unsigned key = f2key(s);
        if (key >= th) {
            unsigned pos = atomicAdd(&s_cnt, 1u);
            if (pos < CAND2)
                g_cand[(size_t)tok * CAND2 + pos] = packc(key, (unsigned)j);
        }
    }
    __syncthreads();
    if (tid == 0) {
        unsigned c = s_cnt;
        g_ccnt[tok] = (c > CAND2) ? CAND2 : c;
    }
}

// ---------------------------------------------------------------------------
// Kernel 4: per-token select: bitonic sort of <=1024 packed candidates,
// softmax over top-256, budget mask.
// ---------------------------------------------------------------------------
#define TPS 512
__global__ void select_kernel() {
    __shared__ unsigned long long c[CAND2];   // 8 KB
    __shared__ float red[256];
    int tid = threadIdx.x;                    // 0..511
    int tok = blockIdx.x;

    unsigned cnt = g_ccnt[tok];
    if (cnt > CAND2) cnt = CAND2;
    for (int i = tid; i < CAND2; i += TPS)
        c[i] = (i < (int)cnt) ? g_cand[(size_t)tok * CAND2 + i] : 0ULL;
    __syncthreads();

    for (unsigned k = 2; k <= CAND2; k <<= 1) {
        for (unsigned j = k >> 1; j > 0; j >>= 1) {
            for (unsigned i = tid; i < CAND2; i += TPS) {
                unsigned ixj = i ^ j;
                if (ixj > i) {
                    bool up = ((i & k) == 0);
                    unsigned long long a = c[i], b = c[ixj];
                    if (up ? (a > b) : (a < b)) { c[i] = b; c[ixj] = a; }
                }
            }
            __syncthreads();
        }
    }

    int bud = g_budget[tok];
    float smax = key2f((unsigned)(c[CAND2 - 1] >> 32));
    float ex = 0.f;
    unsigned long long v = 0ULL;
    if (tid < 256) {
        v  = c[CAND2 - 1 - tid];
        ex = expf(key2f((unsigned)(v >> 32)) - smax);
        red[tid] = ex;
    }
    __syncthreads();
    for (int s = 128; s > 0; s >>= 1) {
        if (tid < s) red[tid] += red[tid + s];
        __syncthreads();
    }
    if (tid < 256) {
        float w = ex / red[0];
        if (tid >= bud) w = 0.f;
        g_topidx[(size_t)tok * KSEL + tid] = (int)(0xFFFFFFFFu - (unsigned)(v & 0xFFFFFFFFull));
        g_topw[(size_t)tok * KSEL + tid]   = w;
    }
}

// ---------------------------------------------------------------------------
// Kernel 5: executor
// ---------------------------------------------------------------------------
__global__ void executor_kernel(const float* __restrict__ x,
                                const float* __restrict__ pool,
                                float* __restrict__ out) {
    __shared__ float xs[DIM];
    __shared__ float partial[8][DIM];
    int tok  = blockIdx.x;
    int tid  = threadIdx.x;
    int warp = tid >> 5;
    int lane = tid & 31;

    for (int i = tid; i < DIM; i += 256) xs[i] = x[(size_t)tok * DIM + i];
    __syncthreads();

    float acc[16];
#pragma unroll
    for (int j = 0; j < 16; j++) acc[j] = 0.f;

    for (int k = warp; k < KSEL; k += 8) {
        float w = g_topw[(size_t)tok * KSEL + k];
        if (w != 0.f) {
            int idx = g_topidx[(size_t)tok * KSEL + k];
            const float* row = pool + (size_t)idx * DIM;
            float r[16];
            float p = 0.f;
#pragma unroll
            for (int j = 0; j < 16; j++) {
                r[j] = __ldg(row + lane + 32 * j);
                p += xs[lane + 32 * j] * r[j];
            }
#pragma unroll
            for (int off = 16; off > 0; off >>= 1)
                p += __shfl_xor_sync(0xffffffffu, p, off);
            float act = tanhf(p) * w;
#pragma unroll
            for (int j = 0; j < 16; j++) acc[j] += act * r[j];
        }
    }

#pragma unroll
    for (int j = 0; j < 16; j++) partial[warp][lane + 32 * j] = acc[j];
    __syncthreads();

    for (int e = tid; e < DIM; e += 256) {
        float s = xs[e];
#pragma unroll
        for (int wp = 0; wp < 8; wp++) s += partial[wp][e];
        out[(size_t)tok * DIM + e] = s;
    }
}

// ---------------------------------------------------------------------------
extern "C" void kernel_launch(void* const* d_in, const int* in_sizes, int n_in,
                              void* d_out, int out_size) {
    const float* x    = (const float*)d_in[0];
    const float* pool = (const float*)d_in[1];
    const float* Wc1  = (const float*)d_in[2];
    const float* bc1  = (const float*)d_in[3];
    const float* Wc2  = (const float*)d_in[4];
    const float* bc2  = (const float*)d_in[5];
    const float* Ws1  = (const float*)d_in[6];
    const float* bs1  = (const float*)d_in[7];
    const float* Ws2  = (const float*)d_in[8];
    const float* bs2  = (const float*)d_in[9];
    float* out = (float*)d_out;

    cudaFuncSetAttribute(gemm_kernel,
                         cudaFuncAttributeMaxDynamicSharedMemorySize,
                         GEMM_SMEM_BYTES);

    dim3 wg(POOLSZ / 256, HID2);
    w2conv_kernel<<<wg, 256>>>(Ws2);

    budget_kernel<<<N_TOK / 16, 128>>>(x, Wc1, bc1, Wc2, bc2);
    hidden_kernel<<<N_TOK / 16, 256>>>(x, Ws1, bs1);
    floor_kernel<<<N_TOK / 8, 256>>>();

    dim3 ggrid(N_TOK / BM, POOLSZ / BN);   // x = m fast -> Ws2 slice reused in L2
    gemm_kernel<<<ggrid, 256, GEMM_SMEM_BYTES>>>(bs2);

    fallback_kernel<<<N_TOK, 256>>>(Ws2, bs2);
    select_kernel<<<N_TOK, TPS>>>();

    executor_kernel<<<N_TOK, 256>>>(x, pool, out);
}

// round 13
// speedup vs baseline: 27.2222x; 1.0268x over previous
#include <cuda_runtime.h>
#include <cuda_bf16.h>
#include <math.h>
#include <stdint.h>

// Problem constants
#define N_TOK   2048
#define DIM     512
#define POOLSZ  65536
#define HIDDEN  256
#define HID2    128         // HIDDEN/2 (bf16 pair words)
#define CHID    128
#define KSEL    256
#define CAND2   1024        // candidate buffer depth per token
#define FLOORZ  2.4f        // floor = FLOORZ*sigma  (E[count]=537, sd=23)

// GEMM tiling (bf16 mma.sync m16n8k16 + ldmatrix)
#define BM 128
#define BN 128
#define BKW 32              // k-pair words per stage (= 64 bf16 k)
#define RS 36               // smem row stride in words (32 data + 4 pad)
#define SAW (BM * RS)       // 4608 words per A stage
#define SBW (BN * RS)       // 4608 words per B stage
#define GEMM_SMEM_WORDS (2 * SAW + 2 * SBW + BN + BM)
#define GEMM_SMEM_BYTES (GEMM_SMEM_WORDS * 4)

// Device scratch
__device__ float              g_h[N_TOK * HIDDEN];            // fp32 hidden (floor, fallback)
__device__ unsigned           g_hb[N_TOK * HID2];             // bf16x2 hidden, k-major rows
__device__ unsigned           g_w2t[(size_t)POOLSZ * HID2];   // bf16x2 Ws2^T rows [n][k] (32 MB)
__device__ float              g_floor[N_TOK];
__device__ unsigned           g_ccnt[N_TOK];
__device__ unsigned long long g_cand[(size_t)N_TOK * CAND2];
__device__ int                g_budget[N_TOK];
__device__ int                g_topidx[N_TOK * KSEL];
__device__ float              g_topw[N_TOK * KSEL];

// key helpers: monotonic float->uint mapping
__device__ __forceinline__ unsigned f2key(float s) {
    unsigned u = __float_as_uint(s);
    return (u & 0x80000000u) ? ~u : (u | 0x80000000u);
}
__device__ __forceinline__ float key2f(unsigned k) {
    return (k & 0x80000000u) ? __uint_as_float(k ^ 0x80000000u)
                             : __uint_as_float(~k);
}
__device__ __forceinline__ unsigned long long packc(unsigned key, unsigned idx) {
    return ((unsigned long long)key << 32) | (unsigned long long)(0xFFFFFFFFu - idx);
}
__device__ __forceinline__ unsigned packbf(float lo, float hi) {
    __nv_bfloat162 t;
    t.x = __float2bfloat16(lo);
    t.y = __float2bfloat16(hi);
    return *(unsigned*)&t;
}

__device__ __forceinline__ void cp_async16(uint32_t saddr, const void* gaddr) {
    asm volatile("cp.async.cg.shared.global [%0], [%1], 16;\n"
                 :: "r"(saddr), "l"(gaddr));
}
__device__ __forceinline__ void cp_commit() {
    asm volatile("cp.async.commit_group;\n");
}
template <int N> __device__ __forceinline__ void cp_wait() {
    asm volatile("cp.async.wait_group %0;\n" :: "n"(N));
}
__device__ __forceinline__ void ldsm_x4(uint32_t* r, uint32_t addr) {
    asm volatile("ldmatrix.sync.aligned.m8n8.x4.shared.b16 {%0,%1,%2,%3}, [%4];"
                 : "=r"(r[0]), "=r"(r[1]), "=r"(r[2]), "=r"(r[3]) : "r"(addr));
}
__device__ __forceinline__ void mma_bf16(float* d, const uint32_t* a, const uint32_t* b) {
    asm volatile(
        "mma.sync.aligned.m16n8k16.row.col.f32.bf16.bf16.f32 "
        "{%0,%1,%2,%3}, {%4,%5,%6,%7}, {%8,%9}, {%0,%1,%2,%3};"
        : "+f"(d[0]), "+f"(d[1]), "+f"(d[2]), "+f"(d[3])
        : "r"(a[0]), "r"(a[1]), "r"(a[2]), "r"(a[3]), "r"(b[0]), "r"(b[1]));
}

// ---------------------------------------------------------------------------
// Kernel 0: transpose-convert Ws2 fp32 [HIDDEN][POOLSZ] -> bf16x2 rows [n][k]
// ---------------------------------------------------------------------------
__global__ void w2t_kernel(const float* __restrict__ Ws2) {
    __shared__ float ts[64][65];
    int tid = threadIdx.x;            // 0..255
    int n0 = blockIdx.x * 64;
    int k0 = blockIdx.y * 64;

#pragma unroll
    for (int i = 0; i < 16; i++) {
        int idx = tid + i * 256;
        int k = idx >> 6, n = idx & 63;
        ts[k][n] = Ws2[(size_t)(k0 + k) * POOLSZ + n0 + n];
    }
    __syncthreads();

#pragma unroll
    for (int i = 0; i < 8; i++) {
        int idx = tid + i * 256;
        int n = idx >> 5, w = idx & 31;
        g_w2t[(size_t)(n0 + n) * HID2 + (k0 >> 1) + w] =
            packbf(ts[2 * w][n], ts[2 * w + 1][n]);
    }
}

// ---------------------------------------------------------------------------
// Kernel 1: complexity net -> budget[token]
// ---------------------------------------------------------------------------
__global__ void budget_kernel(const float* __restrict__ x,
                              const float* __restrict__ Wc1,
                              const float* __restrict__ bc1,
                              const float* __restrict__ Wc2,
                              const float* __restrict__ bc2) {
    __shared__ float xs[16][DIM];
    __shared__ float red[16][CHID];
    int tid = threadIdx.x;            // 0..127
    int t0  = blockIdx.x * 16;

    const float4* xsrc = (const float4*)(x + (size_t)t0 * DIM);
    float4* xdst = (float4*)&xs[0][0];
    for (int i = tid; i < 16 * DIM / 4; i += 128) xdst[i] = xsrc[i];
    __syncthreads();

    float acc[16];
#pragma unroll
    for (int m = 0; m < 16; m++) acc[m] = 0.f;

    for (int i = 0; i < DIM; i += 4) {
        float w0 = Wc1[(i + 0) * CHID + tid];
        float w1 = Wc1[(i + 1) * CHID + tid];
        float w2 = Wc1[(i + 2) * CHID + tid];
        float w3 = Wc1[(i + 3) * CHID + tid];
#pragma unroll
        for (int m = 0; m < 16; m++) {
            float4 xv = *(const float4*)&xs[m][i];
            acc[m] += xv.x * w0 + xv.y * w1 + xv.z * w2 + xv.w * w3;
        }
    }

    float b1  = bc1[tid];
    float wc2 = Wc2[tid];
#pragma unroll
    for (int m = 0; m < 16; m++) red[m][tid] = fmaxf(acc[m] + b1, 0.f) * wc2;
    __syncthreads();

    if (tid < 16) {
        float s = bc2[0];
        for (int t = 0; t < CHID; t++) s += red[tid][t];
        float sig   = 1.f / (1.f + expf(-s));
        float scale = sig * sig;
        float raw   = 100.f + 156.f * scale;
        raw = fminf(fmaxf(raw, 100.f), 256.f);
        g_budget[t0 + tid] = (int)rintf(raw);
    }
}

// ---------------------------------------------------------------------------
// Kernel 2: scorer hidden h = relu(x @ Ws1 + bs1); stores fp32 + bf16x2
// ---------------------------------------------------------------------------
__global__ void hidden_kernel(const float* __restrict__ x,
                              const float* __restrict__ Ws1,
                              const float* __restrict__ bs1) {
    __shared__ float xs[16][DIM];
    int tid = threadIdx.x;            // 0..255 (= hidden unit)
    int t0  = blockIdx.x * 16;

    const float4* xsrc = (const float4*)(x + (size_t)t0 * DIM);
    float4* xdst = (float4*)&xs[0][0];
    for (int i = tid; i < 16 * DIM / 4; i += 256) xdst[i] = xsrc[i];
    __syncthreads();

    float acc[16];
#pragma unroll
    for (int m = 0; m < 16; m++) acc[m] = 0.f;

    for (int i = 0; i < DIM; i += 4) {
        float w0 = Ws1[(i + 0) * HIDDEN + tid];
        float w1 = Ws1[(i + 1) * HIDDEN + tid];
        float w2 = Ws1[(i + 2) * HIDDEN + tid];
        float w3 = Ws1[(i + 3) * HIDDEN + tid];
#pragma unroll
        for (int m = 0; m < 16; m++) {
            float4 xv = *(const float4*)&xs[m][i];
            acc[m] += xv.x * w0 + xv.y * w1 + xv.z * w2 + xv.w * w3;
        }
    }

    float b = bs1[tid];
#pragma unroll
    for (int m = 0; m < 16; m++) {
        float hv = fmaxf(acc[m] + b, 0.f);
        g_h[(size_t)(t0 + m) * HIDDEN + tid] = hv;
        float other = __shfl_xor_sync(0xffffffffu, hv, 1);
        if ((tid & 1) == 0)
            g_hb[(size_t)(t0 + m) * HID2 + (tid >> 1)] = packbf(hv, other);
    }
}

// ---------------------------------------------------------------------------
// Kernel 2b: per-token floor = FLOORZ * ||h|| / 16; zero candidate counter
// ---------------------------------------------------------------------------
__global__ void floor_kernel() {
    int tok  = blockIdx.x * 8 + (threadIdx.x >> 5);
    int lane = threadIdx.x & 31;
    const float* h = g_h + (size_t)tok * HIDDEN;
    float s = 0.f;
    for (int i = lane; i < HIDDEN; i += 32) { float v = h[i]; s += v * v; }
#pragma unroll
    for (int off = 16; off > 0; off >>= 1)
        s += __shfl_xor_sync(0xffffffffu, s, off);
    if (lane == 0) {
        g_floor[tok] = FLOORZ * sqrtf(s) * (1.0f / 16.0f);
        g_ccnt[tok]  = 0;
    }
}

// ---------------------------------------------------------------------------
// Kernel 3: bf16 mma.sync GEMM, ldmatrix fragment loads, fused filter.
// CTA 128x128, BK=64 (32 pair words), 8 warps (2m x 4n), warp tile 64x32.
// A smem [m][k] rows, B smem [n][k] rows, stride 36 words (LDSM conflict-free:
// 8 rows -> chunk offsets 4i mod 32, all distinct). cp.async double buffered.
// Epilogue: score >= floor[token] -> push packed candidate; no score store.
// ---------------------------------------------------------------------------
__global__ __launch_bounds__(256, 2) void gemm_kernel(const float* __restrict__ bs2) {
    extern __shared__ unsigned smem[];             // word-addressed
    float* bias_s  = (float*)(smem + 2 * SAW + 2 * SBW);
    float* floor_s = bias_s + BN;

    int tid  = threadIdx.x;
    int warp = tid >> 5, lane = tid & 31;
    int wm = warp >> 2, wn = warp & 3;             // 2 x 4 warps
    int g  = lane >> 2, tg = lane & 3;
    int m0 = blockIdx.x * BM;
    int n0 = blockIdx.y * BN;

    for (int i = tid; i < BN; i += 256) bias_s[i]  = bs2[n0 + i];
    for (int i = tid; i < BM; i += 256) floor_s[i] = g_floor[m0 + i];

    uint32_t sbase = (uint32_t)__cvta_generic_to_shared(smem);
    const unsigned* gA = g_hb + (size_t)m0 * HID2;
    const unsigned* gB = g_w2t + (size_t)n0 * HID2;

    // staging: 1024 16B chunks per operand per stage; 256 threads x 4 iters
    int srow = tid >> 3;                 // 0..31 -> +32*i
    int sc16 = (tid & 7) << 2;           // word quad within 32-word k row

    // ldmatrix per-thread source row/column constants
    int lmat = lane >> 3;                // matrix index 0..3
    int lrow = lane & 7;                 // row within 8x8 matrix
    // A x4 (frame mt): row = wm*64 + mt*16 + (lmat&1)*8 + lrow, kw = (lmat>>1)*4
    int a_row = wm * 64 + (lmat & 1) * 8 + lrow;
    int a_kw  = (lmat >> 1) * 4;
    // B x4 (frame pair p): row = wn*32 + (2p + (lmat>>1))*8 + lrow, kw = (lmat&1)*4
    int b_row = wn * 32 + (lmat >> 1) * 8 + lrow;
    int b_kw  = (lmat & 1) * 4;

    // prologue: stage 0
#pragma unroll
    for (int i = 0; i < 4; i++) {
        int row = srow + i * 32;
        cp_async16(sbase + (uint32_t)((row * RS + sc16) * 4),
                   gA + (size_t)row * HID2 + sc16);
    }
#pragma unroll
    for (int i = 0; i < 4; i++) {
        int row = srow + i * 32;
        cp_async16(sbase + (uint32_t)((2 * SAW + row * RS + sc16) * 4),
                   gB + (size_t)row * HID2 + sc16);
    }
    cp_commit();

    float acc[4][4][4];
#pragma unroll
    for (int mt = 0; mt < 4; mt++)
#pragma unroll
        for (int nt = 0; nt < 4; nt++)
#pragma unroll
            for (int c = 0; c < 4; c++) acc[mt][nt][c] = 0.f;

    for (int it = 0; it < HID2 / BKW; it++) {      // 4 stages
        int buf = it & 1;
        if (it < HID2 / BKW - 1) {
            int kb   = (it + 1) * BKW;
            int nbuf = buf ^ 1;
#pragma unroll
            for (int i = 0; i < 4; i++) {
                int row = srow + i * 32;
                cp_async16(sbase + (uint32_t)((nbuf * SAW + row * RS + sc16) * 4),
                           gA + (size_t)row * HID2 + kb + sc16);
            }
#pragma unroll
            for (int i = 0; i < 4; i++) {
                int row = srow + i * 32;
                cp_async16(sbase + (uint32_t)((2 * SAW + nbuf * SBW + row * RS + sc16) * 4),
                           gB + (size_t)row * HID2 + kb + sc16);
            }
            cp_commit();
            cp_wait<1>();
        } else {
            cp_wait<0>();
        }
        __syncthreads();

        uint32_t abase = sbase + (uint32_t)(buf * SAW * 4);
        uint32_t bbase = sbase + (uint32_t)((2 * SAW + buf * SBW) * 4);

#pragma unroll
        for (int kk = 0; kk < 4; kk++) {           // 4 k16 steps per stage
            uint32_t af[4][4];
#pragma unroll
            for (int mt = 0; mt < 4; mt++)
                ldsm_x4(af[mt], abase +
                        (uint32_t)(((a_row + mt * 16) * RS + kk * 8 + a_kw) * 4));
            uint32_t bf[2][4];
#pragma unroll
            for (int p = 0; p < 2; p++)
                ldsm_x4(bf[p], bbase +
                        (uint32_t)(((b_row + p * 16) * RS + kk * 8 + b_kw) * 4));
#pragma unroll
            for (int mt = 0; mt < 4; mt++)
#pragma unroll
                for (int nt = 0; nt < 4; nt++)
                    mma_bf16(acc[mt][nt], af[mt], &bf[nt >> 1][(nt & 1) * 2]);
        }
        __syncthreads();
    }

    // epilogue: bias + candidate filter (no score store)
#pragma unroll
    for (int mt = 0; mt < 4; mt++) {
#pragma unroll
        for (int c = 0; c < 4; c++) {
            int m_loc = wm * 64 + mt * 16 + g + ((c & 2) ? 8 : 0);
            float flo = floor_s[m_loc];
            int m = m0 + m_loc;
#pragma unroll
            for (int nt = 0; nt < 4; nt++) {
                int n_loc = wn * 32 + nt * 8 + 2 * tg + (c & 1);
                float s = acc[mt][nt][c] + bias_s[n_loc];
                if (s >= flo) {
                    unsigned pos = atomicAdd(&g_ccnt[m], 1u);
                    if (pos < CAND2)
                        g_cand[(size_t)m * CAND2 + pos] =
                            packc(f2key(s), (unsigned)(n0 + n_loc));
                }
            }
        }
    }
}

// ---------------------------------------------------------------------------
// Kernel 3b: fallback for tokens whose candidate count is out of range.
// Recomputes the full score row (fp32) + exact histogram select. Early-exits.
// ---------------------------------------------------------------------------
#define HB 8192
__global__ void fallback_kernel(const float* __restrict__ Ws2,
                                const float* __restrict__ bs2) {
    int tok = blockIdx.x;
    unsigned cnt0 = g_ccnt[tok];
    if (cnt0 >= KSEL && cnt0 <= CAND2) return;

    __shared__ float    hs[HIDDEN];
    __shared__ unsigned hist[HB];
    __shared__ unsigned bsum[256];
    __shared__ unsigned s_thresh, s_cnt;
    int tid = threadIdx.x;            // 0..255

    for (int i = tid; i < HIDDEN; i += 256) hs[i] = g_h[(size_t)tok * HIDDEN + i];
    for (int i = tid; i < HB; i += 256) hist[i] = 0;
    if (tid == 0) s_cnt = 0;
    __syncthreads();

    for (int j0 = 0; j0 < POOLSZ; j0 += 256) {
        int j = j0 + tid;
        float s = bs2[j];
        for (int k = 0; k < HIDDEN; k += 4) {
            float4 hv = *(const float4*)&hs[k];
            s += hv.x * Ws2[(size_t)(k + 0) * POOLSZ + j];
            s += hv.y * Ws2[(size_t)(k + 1) * POOLSZ + j];
            s += hv.z * Ws2[(size_t)(k + 2) * POOLSZ + j];
            s += hv.w * Ws2[(size_t)(k + 3) * POOLSZ + j];
        }
        atomicAdd(&hist[f2key(s) >> 19], 1u);
    }
    __syncthreads();

    unsigned local = 0;
    int bb = tid * 32;
#pragma unroll
    for (int b = 0; b < 32; b++) local += hist[bb + b];
    bsum[tid] = local;
    __syncthreads();
    if (tid == 0) {
        unsigned cum = 0;
        int blk = 255;
        for (; blk > 0; blk--) {
            if (cum + bsum[blk] >= KSEL) break;
            cum += bsum[blk];
        }
        int b = blk * 32 + 31;
        for (;; b--) {
            unsigned c = hist[b];
            if (cum + c >= KSEL || b == 0) break;
            cum += c;
        }
        s_thresh = (unsigned)b << 19;
    }
    __syncthreads();
    unsigned th = s_thresh;

    for (int j0 = 0; j0 < POOLSZ; j0 += 256) {
        int j = j0 + tid;
        float s = bs2[j];
        for (int k = 0; k < HIDDEN; k += 4) {
            float4 hv = *(const float4*)&hs[k];
            s += hv.x * Ws2[(size_t)(k + 0) * POOLSZ + j];
            s += hv.y * Ws2[(size_t)(k + 1) * POOLSZ + j];
            s += hv.z * Ws2[(size_t)(k + 2) * POOLSZ + j];
            s += hv.w * Ws2[(size_t)(k + 3) * POOLSZ + j];
        }
        unsigned key = f2key(s);
        if (key >= th) {
            unsigned pos = atomicAdd(&s_cnt, 1u);
            if (pos < CAND2)
                g_cand[(size_t)tok * CAND2 + pos] = packc(key, (unsigned)j);
        }
    }
    __syncthreads();
    if (tid == 0) {
        unsigned c = s_cnt;
        g_ccnt[tok] = (c > CAND2) ? CAND2 : c;
    }
}

// ---------------------------------------------------------------------------
// Kernel 4: per-token select: bitonic sort of <=1024 packed candidates,
// softmax over top-256, budget mask.
// ---------------------------------------------------------------------------
#define TPS 512
__global__ void select_kernel() {
    __shared__ unsigned long long c[CAND2];
    __shared__ float red[256];
    int tid = threadIdx.x;
    int tok = blockIdx.x;

    unsigned cnt = g_ccnt[tok];
    if (cnt > CAND2) cnt = CAND2;
    for (int i = tid; i < CAND2; i += TPS)
        c[i] = (i < (int)cnt) ? g_cand[(size_t)tok * CAND2 + i] : 0ULL;
    __syncthreads();

    for (unsigned k = 2; k <= CAND2; k <<= 1) {
        for (unsigned j = k >> 1; j > 0; j >>= 1) {
            for (unsigned i = tid; i < CAND2; i += TPS) {
                unsigned ixj = i ^ j;
                if (ixj > i) {
                    bool up = ((i & k) == 0);
                    unsigned long long a = c[i], b = c[ixj];
                    if (up ? (a > b) : (a < b)) { c[i] = b; c[ixj] = a; }
                }
            }
            __syncthreads();
        }
    }

    int bud = g_budget[tok];
    float smax = key2f((unsigned)(c[CAND2 - 1] >> 32));
    float ex = 0.f;
    unsigned long long v = 0ULL;
    if (tid < 256) {
        v  = c[CAND2 - 1 - tid];
        ex = expf(key2f((unsigned)(v >> 32)) - smax);
        red[tid] = ex;
    }
    __syncthreads();
    for (int s = 128; s > 0; s >>= 1) {
        if (tid < s) red[tid] += red[tid + s];
        __syncthreads();
    }
    if (tid < 256) {
        float w = ex / red[0];
        if (tid >= bud) w = 0.f;
        g_topidx[(size_t)tok * KSEL + tid] = (int)(0xFFFFFFFFu - (unsigned)(v & 0xFFFFFFFFull));
        g_topw[(size_t)tok * KSEL + tid]   = w;
    }
}

// ---------------------------------------------------------------------------
// Kernel 5: executor
// ---------------------------------------------------------------------------
__global__ void executor_kernel(const float* __restrict__ x,
                                const float* __restrict__ pool,
                                float* __restrict__ out) {
    __shared__ float xs[DIM];
    __shared__ float partial[8][DIM];
    int tok  = blockIdx.x;
    int tid  = threadIdx.x;
    int warp = tid >> 5;
    int lane = tid & 31;

    for (int i = tid; i < DIM; i += 256) xs[i] = x[(size_t)tok * DIM + i];
    __syncthreads();

    float acc[16];
#pragma unroll
    for (int j = 0; j < 16; j++) acc[j] = 0.f;

    for (int k = warp; k < KSEL; k += 8) {
        float w = g_topw[(size_t)tok * KSEL + k];
        if (w != 0.f) {
            int idx = g_topidx[(size_t)tok * KSEL + k];
            const float* row = pool + (size_t)idx * DIM;
            float r[16];
            float p = 0.f;
#pragma unroll
            for (int j = 0; j < 16; j++) {
                r[j] = __ldg(row + lane + 32 * j);
                p += xs[lane + 32 * j] * r[j];
            }
#pragma unroll
            for (int off = 16; off > 0; off >>= 1)
                p += __shfl_xor_sync(0xffffffffu, p, off);
            float act = tanhf(p) * w;
#pragma unroll
            for (int j = 0; j < 16; j++) acc[j] += act * r[j];
        }
    }

#pragma unroll
    for (int j = 0; j < 16; j++) partial[warp][lane + 32 * j] = acc[j];
    __syncthreads();

    for (int e = tid; e < DIM; e += 256) {
        float s = xs[e];
#pragma unroll
        for (int wp = 0; wp < 8; wp++) s += partial[wp][e];
        out[(size_t)tok * DIM + e] = s;
    }
}

// ---------------------------------------------------------------------------
extern "C" void kernel_launch(void* const* d_in, const int* in_sizes, int n_in,
                              void* d_out, int out_size) {
    const float* x    = (const float*)d_in[0];
    const float* pool = (const float*)d_in[1];
    const float* Wc1  = (const float*)d_in[2];
    const float* bc1  = (const float*)d_in[3];
    const float* Wc2  = (const float*)d_in[4];
    const float* bc2  = (const float*)d_in[5];
    const float* Ws1  = (const float*)d_in[6];
    const float* bs1  = (const float*)d_in[7];
    const float* Ws2  = (const float*)d_in[8];
    const float* bs2  = (const float*)d_in[9];
    float* out = (float*)d_out;

    cudaFuncSetAttribute(gemm_kernel,
                         cudaFuncAttributeMaxDynamicSharedMemorySize,
                         GEMM_SMEM_BYTES);

    dim3 tg(POOLSZ / 64, HIDDEN / 64);
    w2t_kernel<<<tg, 256>>>(Ws2);

    budget_kernel<<<N_TOK / 16, 128>>>(x, Wc1, bc1, Wc2, bc2);
    hidden_kernel<<<N_TOK / 16, 256>>>(x, Ws1, bs1);
    floor_kernel<<<N_TOK / 8, 256>>>();

    dim3 ggrid(N_TOK / BM, POOLSZ / BN);   // x = m fast -> B slice reused in L2
    gemm_kernel<<<ggrid, 256, GEMM_SMEM_BYTES>>>(bs2);

    fallback_kernel<<<N_TOK, 256>>>(Ws2, bs2);
    select_kernel<<<N_TOK, TPS>>>();

    executor_kernel<<<N_TOK, 256>>>(x, pool, out);
}